// round 1
// baseline (speedup 1.0000x reference)
#include <cuda_runtime.h>
#include <cstdint>

#define KM 1024
#define KN 50000
#define CAP 4096
#define LAMBDA 2048.0f

// ---------------- device scratch (static; no allocations) ----------------
__device__ float g_logp[KN];
__device__ __align__(16) float g_uth[KN];
__device__ unsigned long long g_cand[(size_t)KM * CAP];   // ~32 MB
__device__ int   g_cnt[KM];
__device__ int   g_npos[KM];
__device__ float g_s1[KM];
__device__ float g_rowsum[KM];

// ---------------- threefry2x32 with key (0, 42) ----------------
__device__ __forceinline__ void tf_round(unsigned &a, unsigned &b, int r) {
    a += b;
    b = __funnelshift_l(b, b, r);  // rotl
    b ^= a;
}

// x0 = 0 (counts < 2^32 => hi word always 0), x1 = linear index
__device__ __forceinline__ unsigned tf_bits(unsigned L) {
    const unsigned ks0 = 0u, ks1 = 42u, ks2 = 0x1BD11BF0u; // 0 ^ 42 ^ 0x1BD11BDA
    unsigned x0 = ks0;          // 0 + ks0
    unsigned x1 = L + ks1;
    tf_round(x0,x1,13); tf_round(x0,x1,15); tf_round(x0,x1,26); tf_round(x0,x1,6);
    x0 += ks1; x1 += ks2 + 1u;
    tf_round(x0,x1,17); tf_round(x0,x1,29); tf_round(x0,x1,16); tf_round(x0,x1,24);
    x0 += ks2; x1 += ks0 + 2u;
    tf_round(x0,x1,13); tf_round(x0,x1,15); tf_round(x0,x1,26); tf_round(x0,x1,6);
    x0 += ks0; x1 += ks1 + 3u;
    tf_round(x0,x1,17); tf_round(x0,x1,29); tf_round(x0,x1,16); tf_round(x0,x1,24);
    x0 += ks1; x1 += ks2 + 4u;
    tf_round(x0,x1,13); tf_round(x0,x1,15); tf_round(x0,x1,26); tf_round(x0,x1,6);
    x0 += ks2; x1 += ks0 + 5u;
    // partitionable threefry, 32-bit draw: fold the two outputs
    return x0 ^ x1;
}

// stable log(sigmoid(x)) matching jax.nn.log_sigmoid within ulps
__device__ __forceinline__ float logsig(float x) {
    float z = -fabsf(x);
    float l = log1pf(expf(z));
    return (x >= 0.f) ? -l : (x - l);
}

// ---------------- kernel 0: per-column tables ----------------
__global__ void k_setup(const float* __restrict__ noise) {
    int j = blockIdx.x * blockDim.x + threadIdx.x;
    if (j < KN) {
        float p = noise[j];
        g_logp[j] = logf(p);
        // conservative prefilter: keeps every item whose score could be within
        // the top ~512 of its row (true k <= ~150); 0.9995 covers fp slop
        g_uth[j] = expf(-LAMBDA * p) * 0.9995f;
    }
}

// ---------------- kernel 1: scan rows, count positives, s1, candidates ----------------
__global__ __launch_bounds__(256) void k_scan(const float* __restrict__ outp,
                                              const float* __restrict__ tgt) {
    const int r   = blockIdx.x;
    const int tid = threadIdx.x;
    __shared__ int   s_cnt;
    __shared__ float s_f[8];
    __shared__ int   s_i[8];
    if (tid == 0) s_cnt = 0;
    __syncthreads();

    const float4* t4 = (const float4*)(tgt + (size_t)r * KN);
    const float4* u4 = (const float4*)g_uth;
    const unsigned base = (unsigned)r * (unsigned)KN;

    float s1 = 0.f;
    int   np = 0;

    for (int q = tid; q < KN / 4; q += 256) {
        float4 tv4 = t4[q];
        float4 uv4 = u4[q];
        float tv[4] = {tv4.x, tv4.y, tv4.z, tv4.w};
        float uv[4] = {uv4.x, uv4.y, uv4.z, uv4.w};
        int j0 = q * 4;
        #pragma unroll
        for (int e = 0; e < 4; e++) {
            int j = j0 + e;
            unsigned bits = tf_bits(base + (unsigned)j);
            float u = __uint_as_float((bits >> 9) | 0x3F800000u) - 1.0f;
            if (u >= uv[e]) {
                float uu = fmaxf(u, 1.17549435e-38f);
                float g  = -logf(-logf(uu));
                float s  = g_logp[j] + g;
                unsigned sb = __float_as_uint(s);
                sb = (sb & 0x80000000u) ? ~sb : (sb | 0x80000000u); // monotone map
                unsigned long long key =
                    ((unsigned long long)sb << 32) | (0xFFFFFFFFu - (unsigned)j);
                int slot = atomicAdd(&s_cnt, 1);
                if (slot < CAP) g_cand[(size_t)r * CAP + slot] = key;
            }
            if (tv[e] != 0.0f) {
                np++;
                s1 += tv[e] * logsig(outp[(size_t)r * KN + j]);
            }
        }
    }

    // block reduce
    #pragma unroll
    for (int off = 16; off; off >>= 1) {
        s1 += __shfl_down_sync(0xFFFFFFFFu, s1, off);
        np += __shfl_down_sync(0xFFFFFFFFu, np, off);
    }
    if ((tid & 31) == 0) { s_f[tid >> 5] = s1; s_i[tid >> 5] = np; }
    __syncthreads();
    if (tid == 0) {
        float a = 0.f; int b = 0;
        #pragma unroll
        for (int i = 0; i < 8; i++) { a += s_f[i]; b += s_i[i]; }
        g_s1[r]   = a;
        g_npos[r] = b;
        g_cnt[r]  = s_cnt;
    }
}

// ---------------- kernel 2: exact top-k via radix select, compute s2 ----------------
__global__ __launch_bounds__(256) void k_select(const float* __restrict__ outp,
                                                const int* __restrict__ pneg) {
    __shared__ unsigned long long sk[CAP];
    __shared__ unsigned int hist[256];
    __shared__ int s_bin, s_rem;
    __shared__ float s_f[8];

    const int r   = blockIdx.x;
    const int tid = threadIdx.x;
    int c = g_cnt[r]; if (c > CAP) c = CAP;
    int k = g_npos[r] * pneg[0]; if (k > KN) k = KN;
    int sel = (k < c) ? k : c;

    float s2 = 0.f;
    if (sel > 0) {
        for (int i = tid; i < c; i += 256) sk[i] = g_cand[(size_t)r * CAP + i];
        if (tid == 0) s_rem = sel;
        __syncthreads();

        unsigned long long prefix = 0ull;
        for (int shift = 56; shift >= 0; shift -= 8) {
            hist[tid & 255] = 0;   // 256 threads, 256 bins
            __syncthreads();
            unsigned long long mask = (shift == 56) ? 0ull : (~0ull << (shift + 8));
            for (int i = tid; i < c; i += 256) {
                unsigned long long key = sk[i];
                if ((key & mask) == prefix)
                    atomicAdd(&hist[(unsigned)(key >> shift) & 0xFFu], 1u);
            }
            __syncthreads();
            if (tid == 0) {
                int rem = s_rem, cum = 0, b = 255;
                for (;; b--) {
                    int h = (int)hist[b];
                    if (cum + h >= rem || b == 0) { s_bin = b; s_rem = rem - cum; break; }
                    cum += h;
                }
            }
            __syncthreads();
            prefix |= ((unsigned long long)(unsigned)s_bin) << shift;
        }
        // keys are unique => exactly `sel` keys >= prefix
        for (int i = tid; i < c; i += 256) {
            unsigned long long key = sk[i];
            if (key >= prefix) {
                unsigned idx = 0xFFFFFFFFu - (unsigned)(key & 0xFFFFFFFFull);
                float x = outp[(size_t)r * KN + idx];
                s2 += logsig(-x);
            }
        }
    }

    #pragma unroll
    for (int off = 16; off; off >>= 1)
        s2 += __shfl_down_sync(0xFFFFFFFFu, s2, off);
    if ((tid & 31) == 0) s_f[tid >> 5] = s2;
    __syncthreads();
    if (tid == 0) {
        float tot = 0.f;
        #pragma unroll
        for (int i = 0; i < 8; i++) tot += s_f[i];
        g_rowsum[r] = g_s1[r] + tot;
    }
}

// ---------------- kernel 3: final deterministic reduction ----------------
__global__ __launch_bounds__(256) void k_final(float* outv) {
    __shared__ float s_f[8];
    const int tid = threadIdx.x;
    float s = 0.f;
    for (int i = tid; i < KM; i += 256) s += g_rowsum[i];
    #pragma unroll
    for (int off = 16; off; off >>= 1)
        s += __shfl_down_sync(0xFFFFFFFFu, s, off);
    if ((tid & 31) == 0) s_f[tid >> 5] = s;
    __syncthreads();
    if (tid == 0) {
        float tot = 0.f;
        #pragma unroll
        for (int i = 0; i < 8; i++) tot += s_f[i];
        outv[0] = -(tot / (float)KM);
    }
}

// ---------------- launch ----------------
extern "C" void kernel_launch(void* const* d_in, const int* in_sizes, int n_in,
                              void* d_out, int out_size) {
    const float* outp  = (const float*)d_in[0];   // [1024, 50000]
    const float* tgt   = (const float*)d_in[1];   // [1024, 50000]
    const float* noise = (const float*)d_in[2];   // [50000]
    const int*   pneg  = (const int*)d_in[3];     // scalar
    float* ov = (float*)d_out;

    k_setup<<<(KN + 255) / 256, 256>>>(noise);
    k_scan<<<KM, 256>>>(outp, tgt);
    k_select<<<KM, 256>>>(outp, pneg);
    k_final<<<1, 256>>>(ov);
}

// round 4
// speedup vs baseline: 1.7085x; 1.7085x over previous
#include <cuda_runtime.h>
#include <cstdint>

#define KM 1024
#define KN 50000
#define CAP 1024
#define LAMBDA 320.0f

// ---------------- device scratch (static; no allocations) ----------------
__device__ float g_logp[KN];
__device__ __align__(16) unsigned g_th[KN];                 // integer bits threshold
__device__ unsigned long long g_cand[(size_t)KM * CAP];     // (bits<<32)|j, 8 MB
__device__ int   g_cnt[KM];
__device__ int   g_npos[KM];
__device__ float g_s1[KM];
__device__ float g_rowsum[KM];

// ---------------- threefry2x32 with key (0, 42), partitionable fold ----------------
__device__ __forceinline__ void tf_round(unsigned &a, unsigned &b, int r) {
    a += b;
    b = __funnelshift_l(b, b, r);
    b ^= a;
}

__device__ __forceinline__ unsigned tf_bits(unsigned L) {
    const unsigned ks0 = 0u, ks1 = 42u, ks2 = 0x1BD11BF0u;
    unsigned x0 = ks0;
    unsigned x1 = L + ks1;
    tf_round(x0,x1,13); tf_round(x0,x1,15); tf_round(x0,x1,26); tf_round(x0,x1,6);
    x0 += ks1; x1 += ks2 + 1u;
    tf_round(x0,x1,17); tf_round(x0,x1,29); tf_round(x0,x1,16); tf_round(x0,x1,24);
    x0 += ks2; x1 += ks0 + 2u;
    tf_round(x0,x1,13); tf_round(x0,x1,15); tf_round(x0,x1,26); tf_round(x0,x1,6);
    x0 += ks0; x1 += ks1 + 3u;
    tf_round(x0,x1,17); tf_round(x0,x1,29); tf_round(x0,x1,16); tf_round(x0,x1,24);
    x0 += ks1; x1 += ks2 + 4u;
    tf_round(x0,x1,13); tf_round(x0,x1,15); tf_round(x0,x1,26); tf_round(x0,x1,6);
    x0 += ks2; x1 += ks0 + 5u;
    return x0 ^ x1;
}

__device__ __forceinline__ float logsig(float x) {
    float z = -fabsf(x);
    float l = log1pf(expf(z));
    return (x >= 0.f) ? -l : (x - l);
}

// ---------------- kernel 0: per-column tables ----------------
__global__ void k_setup(const float* __restrict__ noise) {
    int j = blockIdx.x * blockDim.x + threadIdx.x;
    if (j < KN) {
        float p = noise[j];
        g_logp[j] = logf(p);
        // filter keeps exactly {score >= -log(LAMBDA)} (E[count] = LAMBDA per row).
        // u >= uth  <=>  raw bits >= ((mantissa of 1+uth) << 9). Slack factors make
        // the kept set a strict superset; selection below is exact among candidates.
        float uth = expf(-LAMBDA * p) * 0.999f;
        unsigned m = __float_as_uint(1.0f + uth) & 0x7FFFFFu;
        unsigned th = m << 9;
        g_th[j] = (th > 4096u) ? th - 4096u : 0u;
    }
}

// ---------------- kernel 1: threefry scan; cheap candidate capture ----------------
__global__ __launch_bounds__(256) void k_scan(const float* __restrict__ outp,
                                              const float* __restrict__ tgt) {
    const int r   = blockIdx.x;
    const int tid = threadIdx.x;
    __shared__ int   s_cnt;
    __shared__ float s_f[8];
    __shared__ int   s_i[8];
    if (tid == 0) s_cnt = 0;
    __syncthreads();

    const float4* t4 = (const float4*)(tgt + (size_t)r * KN);
    const uint4*  h4 = (const uint4*)g_th;
    const unsigned base = (unsigned)r * (unsigned)KN;
    unsigned long long* crow = g_cand + (size_t)r * CAP;

    float s1 = 0.f;
    int   np = 0;

    for (int q = tid; q < KN / 4; q += 256) {
        float4 tv4 = t4[q];
        uint4  th4 = h4[q];
        float tv[4] = {tv4.x, tv4.y, tv4.z, tv4.w};
        unsigned th[4] = {th4.x, th4.y, th4.z, th4.w};
        unsigned j0 = (unsigned)q * 4u;
        #pragma unroll
        for (int e = 0; e < 4; e++) {
            unsigned j = j0 + (unsigned)e;
            unsigned bits = tf_bits(base + j);
            if (bits >= th[e]) {                 // rare (~0.64%): defer all math
                int slot = atomicAdd(&s_cnt, 1);
                if (slot < CAP)
                    crow[slot] = ((unsigned long long)bits << 32) | j;
            }
            if (tv[e] != 0.0f) {                 // rare (~0.02%)
                np++;
                s1 += tv[e] * logsig(outp[(size_t)r * KN + j]);
            }
        }
    }

    #pragma unroll
    for (int off = 16; off; off >>= 1) {
        s1 += __shfl_down_sync(0xFFFFFFFFu, s1, off);
        np += __shfl_down_sync(0xFFFFFFFFu, np, off);
    }
    if ((tid & 31) == 0) { s_f[tid >> 5] = s1; s_i[tid >> 5] = np; }
    __syncthreads();
    if (tid == 0) {
        float a = 0.f; int b = 0;
        #pragma unroll
        for (int i = 0; i < 8; i++) { a += s_f[i]; b += s_i[i]; }
        g_s1[r]   = a;
        g_npos[r] = b;
        g_cnt[r]  = s_cnt;
    }
}

// ---------------- kernel 2: score candidates, exact radix top-k, s2 ----------------
__global__ __launch_bounds__(256) void k_select(const float* __restrict__ outp,
                                                const int* __restrict__ pneg) {
    __shared__ unsigned long long sk[CAP];
    __shared__ unsigned int hist[256];
    __shared__ int s_bin, s_rem, s_done;
    __shared__ float s_f[8];

    const int r   = blockIdx.x;
    const int tid = threadIdx.x;
    int c = g_cnt[r]; if (c > CAP) c = CAP;
    int k = g_npos[r] * pneg[0]; if (k > KN) k = KN;
    int sel = (k < c) ? k : c;

    float s2 = 0.f;
    if (sel > 0) {
        // build sortable keys: (monotone score bits << 32) | (0xFFFFFFFF - idx)
        for (int i = tid; i < c; i += 256) {
            unsigned long long raw = g_cand[(size_t)r * CAP + i];
            unsigned bits = (unsigned)(raw >> 32);
            unsigned j    = (unsigned)(raw & 0xFFFFFFFFull);
            float u = __uint_as_float((bits >> 9) | 0x3F800000u) - 1.0f;
            u = fmaxf(u, 1.17549435e-38f);
            float g = -logf(-logf(u));
            float s = g_logp[j] + g;
            unsigned sb = __float_as_uint(s);
            sb = (sb & 0x80000000u) ? ~sb : (sb | 0x80000000u);
            sk[i] = ((unsigned long long)sb << 32) | (0xFFFFFFFFu - j);
        }
        if (tid == 0) { s_rem = sel; s_done = 0; }
        __syncthreads();

        unsigned long long prefix = 0ull;
        for (int shift = 56; shift >= 0 && !s_done; shift -= 8) {
            hist[tid] = 0;
            __syncthreads();
            unsigned long long mask = (shift == 56) ? 0ull : (~0ull << (shift + 8));
            for (int i = tid; i < c; i += 256) {
                unsigned long long key = sk[i];
                if ((key & mask) == prefix)
                    atomicAdd(&hist[(unsigned)(key >> shift) & 0xFFu], 1u);
            }
            __syncthreads();
            if (tid == 0) {
                int rem = s_rem, cum = 0, b = 255;
                for (;; b--) {
                    int h = (int)hist[b];
                    if (cum + h >= rem || b == 0) {
                        s_bin = b; s_rem = rem - cum;
                        if (h == rem - cum) s_done = 1;  // bin fully selected
                        break;
                    }
                    cum += h;
                }
            }
            __syncthreads();
            prefix |= ((unsigned long long)(unsigned)s_bin) << shift;
        }
        // keys unique => exactly `sel` keys >= prefix (low bytes zero on early exit)
        for (int i = tid; i < c; i += 256) {
            unsigned long long key = sk[i];
            if (key >= prefix) {
                unsigned idx = 0xFFFFFFFFu - (unsigned)(key & 0xFFFFFFFFull);
                s2 += logsig(-outp[(size_t)r * KN + idx]);
            }
        }
    }

    #pragma unroll
    for (int off = 16; off; off >>= 1)
        s2 += __shfl_down_sync(0xFFFFFFFFu, s2, off);
    if ((tid & 31) == 0) s_f[tid >> 5] = s2;
    __syncthreads();
    if (tid == 0) {
        float tot = 0.f;
        #pragma unroll
        for (int i = 0; i < 8; i++) tot += s_f[i];
        g_rowsum[r] = g_s1[r] + tot;
    }
}

// ---------------- kernel 3: final reduction ----------------
__global__ __launch_bounds__(256) void k_final(float* outv) {
    __shared__ float s_f[8];
    const int tid = threadIdx.x;
    float s = 0.f;
    for (int i = tid; i < KM; i += 256) s += g_rowsum[i];
    #pragma unroll
    for (int off = 16; off; off >>= 1)
        s += __shfl_down_sync(0xFFFFFFFFu, s, off);
    if ((tid & 31) == 0) s_f[tid >> 5] = s;
    __syncthreads();
    if (tid == 0) {
        float tot = 0.f;
        #pragma unroll
        for (int i = 0; i < 8; i++) tot += s_f[i];
        outv[0] = -(tot / (float)KM);
    }
}

// ---------------- launch ----------------
extern "C" void kernel_launch(void* const* d_in, const int* in_sizes, int n_in,
                              void* d_out, int out_size) {
    const float* outp  = (const float*)d_in[0];
    const float* tgt   = (const float*)d_in[1];
    const float* noise = (const float*)d_in[2];
    const int*   pneg  = (const int*)d_in[3];
    float* ov = (float*)d_out;

    k_setup<<<(KN + 255) / 256, 256>>>(noise);
    k_scan<<<KM, 256>>>(outp, tgt);
    k_select<<<KM, 256>>>(outp, pneg);
    k_final<<<1, 256>>>(ov);
}